// round 8
// baseline (speedup 1.0000x reference)
#include <cuda_runtime.h>
#include <cuda_fp16.h>
#include <cstdint>

#define N_FEAT 256
#define ROWS 128                       // M rows per CTA

// B in fragment order, global, uint4-packed pairs of interleaved subs:
//   G[jt(4)][kb(16)][jh(2)][pi(2)][lane(32)] -> uint4
//   .x/.y = sub (jh + 4*pi)     k-lo pair / k-hi pair
//   .z/.w = sub (jh + 4*pi + 2) k-lo pair / k-hi pair
// where sub s covers cols j = jt*64 + s*8 + (lane>>2),
//       k-lo = half2(L[k0][j],L[k0+1][j]), k-hi = +8, k0 = kb*16 + (lane&3)*2.
// L[k][j] = W[k][j] if k > j else 0 (strict lower; validated R1).
__device__ __align__(16) uint4 g_Bf[4 * 16 * 2 * 2 * 32];

// ---- smem layout (bytes) ----
#define OFF_AFRAG 0                    // 8 rg x 16 kb x 32 lanes x uint4 = 64KB
#define OFF_WL    65536                // 256 floats
#define OFF_RS    66560                // 128 floats rowsum
#define SMEM_TOTAL 67072

// ---------------------------------------------------------------------------
// Prep: W[k][j] = sum_m v[k,f(j),m] * v[j,f(k),m]  -> fp16 fragments
// ---------------------------------------------------------------------------
__global__ void ffm_prep(const float* __restrict__ v, const int* __restrict__ fidx) {
    int idx = blockIdx.x * blockDim.x + threadIdx.x;   // 0 .. 16383
    if (idx >= 4 * 16 * 8 * 32) return;
    int lane = idx & 31;
    int sub  = (idx >> 5) & 7;
    int kb   = (idx >> 8) & 15;
    int jt   = idx >> 12;
    int g  = lane >> 2, tg = lane & 3;
    int j  = jt * 64 + sub * 8 + g;
    int k0 = kb * 16 + tg * 2;
    int fj = fidx[j];
    const float* vjr = v + (j * 32) * 8;

    float lv[4];
    int kk[4] = {k0, k0 + 1, k0 + 8, k0 + 9};
#pragma unroll
    for (int q = 0; q < 4; ++q) {
        int k = kk[q];
        float s = 0.f;
        if (k > j) {
            int fk = fidx[k];
            const float* a = v + (k * 32 + fj) * 8;
            const float* b = vjr + fk * 8;
#pragma unroll
            for (int m = 0; m < 8; ++m) s += a[m] * b[m];
        }
        lv[q] = s;
    }
    __half2 w0 = __floats2half2_rn(lv[0], lv[1]);
    __half2 w1 = __floats2half2_rn(lv[2], lv[3]);

    // map (sub) -> packed uint4 slot
    int jh   = sub & 1;
    int sl   = sub >> 1;          // 0..3  (acc index s)
    int pi   = sl >> 1;           // pair index
    int half = sl & 1;            // 0 -> .x/.y, 1 -> .z/.w
    int U = (((jt * 16 + kb) * 2 + jh) * 2 + pi) * 32 + lane;
    uint32_t* g32 = reinterpret_cast<uint32_t*>(g_Bf);
    g32[U * 4 + half * 2]     = *reinterpret_cast<uint32_t*>(&w0);
    g32[U * 4 + half * 2 + 1] = *reinterpret_cast<uint32_t*>(&w1);
}

// ---------------------------------------------------------------------------
__device__ __forceinline__ void mma_f16(float c[4], const uint4& a, uint32_t b0, uint32_t b1) {
    asm volatile(
        "mma.sync.aligned.m16n8k16.row.col.f32.f16.f16.f32 "
        "{%0,%1,%2,%3}, {%4,%5,%6,%7}, {%8,%9}, {%0,%1,%2,%3};\n"
        : "+f"(c[0]), "+f"(c[1]), "+f"(c[2]), "+f"(c[3])
        : "r"(a.x), "r"(a.y), "r"(a.z), "r"(a.w), "r"(b0), "r"(b1));
}

// Main: Z = X * L (fp16, fine-grained triangular skip), fused epilogue
//       out[b] = sum_j x[b,j] * (w[j] + Z[b,j]) + b_lin
// 512 threads = 16 warps: warp = rg(0..7) x jhalf(0..1).
// Warp jhalf owns interleaved subs {jhalf, jhalf+2, jhalf+4, jhalf+6} (acc s=0..3)
__global__ __launch_bounds__(512, 2) void ffm_main(
    const float* __restrict__ x, const float* __restrict__ wl,
    const float* __restrict__ bl, float* __restrict__ out, int Bn) {
    extern __shared__ char smem[];
    uint4*  afrag  = reinterpret_cast<uint4*>(smem + OFF_AFRAG);
    float*  wls    = reinterpret_cast<float*>(smem + OFF_WL);
    float*  rowsum = reinterpret_cast<float*>(smem + OFF_RS);

    const int tid  = threadIdx.x;
    const int row0 = blockIdx.x * ROWS;

    if (tid < 256) wls[tid] = wl[tid];
    if (tid < 128) rowsum[tid] = 0.f;

    // ---- stage A fragments: x fp32 -> fp16, mma a-fragment order ----
    for (int it = tid; it < 4096; it += 512) {
        int ln = it & 31;
        int kb = (it >> 5) & 15;
        int rg = it >> 9;
        int g = ln >> 2, tg = ln & 3;
        int r0 = rg * 16 + g, r1 = r0 + 8;
        int c0 = kb * 16 + tg * 2;
        int gr0 = row0 + r0, gr1 = row0 + r1;
        float2 z2 = make_float2(0.f, 0.f);
        float2 v00 = (gr0 < Bn) ? *reinterpret_cast<const float2*>(x + (size_t)gr0 * N_FEAT + c0)     : z2;
        float2 v01 = (gr0 < Bn) ? *reinterpret_cast<const float2*>(x + (size_t)gr0 * N_FEAT + c0 + 8) : z2;
        float2 v10 = (gr1 < Bn) ? *reinterpret_cast<const float2*>(x + (size_t)gr1 * N_FEAT + c0)     : z2;
        float2 v11 = (gr1 < Bn) ? *reinterpret_cast<const float2*>(x + (size_t)gr1 * N_FEAT + c0 + 8) : z2;
        __half2 h00 = __floats2half2_rn(v00.x, v00.y);
        __half2 h10 = __floats2half2_rn(v10.x, v10.y);
        __half2 h01 = __floats2half2_rn(v01.x, v01.y);
        __half2 h11 = __floats2half2_rn(v11.x, v11.y);
        uint4 o;
        o.x = *reinterpret_cast<uint32_t*>(&h00);
        o.y = *reinterpret_cast<uint32_t*>(&h10);
        o.z = *reinterpret_cast<uint32_t*>(&h01);
        o.w = *reinterpret_cast<uint32_t*>(&h11);
        afrag[(rg * 16 + kb) * 32 + ln] = o;
    }
    __syncthreads();

    const int wid = tid >> 5, lane = tid & 31;
    const int rg = wid >> 1, jhalf = wid & 1;
    const int g = lane >> 2, tg = lane & 3;

    float partial0 = 0.f, partial1 = 0.f;

#pragma unroll
    for (int jt = 0; jt < 4; ++jt) {
        float acc[4][4];
#pragma unroll
        for (int s = 0; s < 4; ++s)
#pragma unroll
            for (int q = 0; q < 4; ++q) acc[s][q] = 0.f;

        const uint4* ap = &afrag[(rg * 16 + 4 * jt) * 32 + lane];
        const uint4* bp = &g_Bf[(((jt * 16 + 4 * jt) * 2 + jhalf) * 2) * 32 + lane];

        // ---- diagonal block: kb_l = 0..3, active subs s <= kb_l (rest exactly 0)
        {
            uint4 a0 = ap[0];
            uint2 b0 = *reinterpret_cast<const uint2*>(bp);
            mma_f16(acc[0], a0, b0.x, b0.y);

            uint4 a1 = ap[32];
            uint4 p1 = bp[128];
            mma_f16(acc[0], a1, p1.x, p1.y);
            mma_f16(acc[1], a1, p1.z, p1.w);

            uint4 a2 = ap[64];
            uint4 p2 = bp[256];
            uint2 q2 = *reinterpret_cast<const uint2*>(bp + 256 + 32);
            mma_f16(acc[0], a2, p2.x, p2.y);
            mma_f16(acc[1], a2, p2.z, p2.w);
            mma_f16(acc[2], a2, q2.x, q2.y);

            uint4 a3 = ap[96];
            uint4 p3 = bp[384];
            uint4 r3 = bp[384 + 32];
            mma_f16(acc[0], a3, p3.x, p3.y);
            mma_f16(acc[1], a3, p3.z, p3.w);
            mma_f16(acc[2], a3, r3.x, r3.y);
            mma_f16(acc[3], a3, r3.z, r3.w);
        }

        // ---- uniform region: kb = 4jt+4 .. 15, all 4 subs
#pragma unroll
        for (int u = 0; u < 12 - 4 * jt; ++u) {
            int off = 4 + u;
            uint4 a  = ap[off * 32];
            uint4 p0 = bp[off * 128];
            uint4 p1 = bp[off * 128 + 32];
            mma_f16(acc[0], a, p0.x, p0.y);
            mma_f16(acc[1], a, p0.z, p0.w);
            mma_f16(acc[2], a, p1.x, p1.y);
            mma_f16(acc[3], a, p1.z, p1.w);
        }

        // ---- fused epilogue: partial += (Z + w) .* x over this warp's 32 cols ----
        // acc[s] <-> sub = jhalf + 2s, cols jt*64 + sub*8 + 2tg (+1).
        // x values live in afrag at kb' = 4jt+s; jhalf picks even(.x/.y)/odd(.z/.w) 8-col half.
#pragma unroll
        for (int s = 0; s < 4; ++s) {
            uint4 av = afrag[(rg * 16 + 4 * jt + s) * 32 + lane];
            uint32_t wlo = jhalf ? av.z : av.x;   // row g
            uint32_t whi = jhalf ? av.w : av.y;   // row g+8
            int sub = jhalf + 2 * s;
            int jb = jt * 64 + sub * 8 + tg * 2;
            float w0 = wls[jb], w1 = wls[jb + 1];
            float2 x0 = __half22float2(*reinterpret_cast<__half2*>(&wlo));
            float2 x1 = __half22float2(*reinterpret_cast<__half2*>(&whi));
            partial0 += (acc[s][0] + w0) * x0.x + (acc[s][1] + w1) * x0.y;
            partial1 += (acc[s][2] + w0) * x1.x + (acc[s][3] + w1) * x1.y;
        }
    }

    // reduce over the 4 lanes (tg) sharing each row
    partial0 += __shfl_xor_sync(0xffffffffu, partial0, 1);
    partial0 += __shfl_xor_sync(0xffffffffu, partial0, 2);
    partial1 += __shfl_xor_sync(0xffffffffu, partial1, 1);
    partial1 += __shfl_xor_sync(0xffffffffu, partial1, 2);

    if (tg == 0) {
        atomicAdd(&rowsum[rg * 16 + g],     partial0);
        atomicAdd(&rowsum[rg * 16 + g + 8], partial1);
    }
    __syncthreads();

    if (tid < 128) {
        int gr = row0 + tid;
        if (gr < Bn) out[gr] = rowsum[tid] + bl[0];
    }
}

// ---------------------------------------------------------------------------
extern "C" void kernel_launch(void* const* d_in, const int* in_sizes, int n_in,
                              void* d_out, int out_size) {
    const float* x    = (const float*)d_in[0];
    const float* wlin = (const float*)d_in[1];
    const float* blin = (const float*)d_in[2];
    const float* v    = (const float*)d_in[3];
    const int*   fidx = (const int*)d_in[4];
    float* out = (float*)d_out;

    int Bn = in_sizes[0] / N_FEAT;

    ffm_prep<<<32, 512>>>(v, fidx);

    cudaFuncSetAttribute(ffm_main, cudaFuncAttributeMaxDynamicSharedMemorySize, SMEM_TOTAL);
    int grid = (Bn + ROWS - 1) / ROWS;
    ffm_main<<<grid, 512, SMEM_TOTAL>>>(x, wlin, blin, out, Bn);
}

// round 9
// speedup vs baseline: 1.2838x; 1.2838x over previous
#include <cuda_runtime.h>
#include <cuda_fp16.h>
#include <cstdint>

#define N_FEAT 256
#define ROWS 128                       // M rows per CTA

// B in fragment order, global, uint4-packed pairs of interleaved subs:
//   G[jt(4)][kb(16)][jh(2)][pi(2)][lane(32)] -> uint4
//   pi=0: .x/.y = acc s=0 (sub=jh)   k-lo/k-hi,  .z/.w = acc s=1 (sub=jh+2)
//   pi=1: .x/.y = acc s=2 (sub=jh+4),            .z/.w = acc s=3 (sub=jh+6)
// sub s covers cols j = jt*64 + sub*8 + (lane>>2),
// k-lo = half2(L[k0][j],L[k0+1][j]), k-hi = +8, k0 = kb*16 + (lane&3)*2.
// L[k][j] = W[k][j] if k > j else 0 (strict lower; validated R1).
__device__ __align__(16) uint4 g_Bf[4 * 16 * 2 * 2 * 32];

// ---- smem layout (bytes) ----
#define OFF_AFRAG 0                    // 8 rg x 16 kb x 32 lanes x uint4 = 64KB
#define OFF_WL    65536                // 256 floats
#define OFF_RS    66560                // 128 floats rowsum
#define SMEM_TOTAL 67072

// ---------------------------------------------------------------------------
// Prep: W[k][j] = sum_m v[k,f(j),m] * v[j,f(k),m]  -> fp16 fragments
// ---------------------------------------------------------------------------
__global__ void ffm_prep(const float* __restrict__ v, const int* __restrict__ fidx) {
    int idx = blockIdx.x * blockDim.x + threadIdx.x;   // 0 .. 16383
    if (idx >= 4 * 16 * 8 * 32) return;
    int lane = idx & 31;
    int sub  = (idx >> 5) & 7;
    int kb   = (idx >> 8) & 15;
    int jt   = idx >> 12;
    int g  = lane >> 2, tg = lane & 3;
    int j  = jt * 64 + sub * 8 + g;
    int k0 = kb * 16 + tg * 2;
    int fj = fidx[j];
    const float* vjr = v + (j * 32) * 8;

    float lv[4];
    int kk[4] = {k0, k0 + 1, k0 + 8, k0 + 9};
#pragma unroll
    for (int q = 0; q < 4; ++q) {
        int k = kk[q];
        float s = 0.f;
        if (k > j) {
            int fk = fidx[k];
            const float* a = v + (k * 32 + fj) * 8;
            const float* b = vjr + fk * 8;
#pragma unroll
            for (int m = 0; m < 8; ++m) s += a[m] * b[m];
        }
        lv[q] = s;
    }
    __half2 w0 = __floats2half2_rn(lv[0], lv[1]);
    __half2 w1 = __floats2half2_rn(lv[2], lv[3]);

    int jh   = sub & 1;
    int sl   = sub >> 1;          // acc index s
    int pi   = sl >> 1;
    int half = sl & 1;
    int U = (((jt * 16 + kb) * 2 + jh) * 2 + pi) * 32 + lane;
    uint32_t* g32 = reinterpret_cast<uint32_t*>(g_Bf);
    g32[U * 4 + half * 2]     = *reinterpret_cast<uint32_t*>(&w0);
    g32[U * 4 + half * 2 + 1] = *reinterpret_cast<uint32_t*>(&w1);
}

// ---------------------------------------------------------------------------
__device__ __forceinline__ void mma_f16(float c[4], const uint4& a, uint32_t b0, uint32_t b1) {
    asm volatile(
        "mma.sync.aligned.m16n8k16.row.col.f32.f16.f16.f32 "
        "{%0,%1,%2,%3}, {%4,%5,%6,%7}, {%8,%9}, {%0,%1,%2,%3};\n"
        : "+f"(c[0]), "+f"(c[1]), "+f"(c[2]), "+f"(c[3])
        : "r"(a.x), "r"(a.y), "r"(a.z), "r"(a.w), "r"(b0), "r"(b1));
}

// Main: Z = X * L (fp16, balanced diagonal skip, prefetch-pipelined), fused epilogue
// 512 threads = 16 warps: warp = rg(0..7) x jhalf(0..1); interleaved subs.
__global__ __launch_bounds__(512, 2) void ffm_main(
    const float* __restrict__ x, const float* __restrict__ wl,
    const float* __restrict__ bl, float* __restrict__ out, int Bn) {
    extern __shared__ char smem[];
    uint4*  afrag  = reinterpret_cast<uint4*>(smem + OFF_AFRAG);
    float*  wls    = reinterpret_cast<float*>(smem + OFF_WL);
    float*  rowsum = reinterpret_cast<float*>(smem + OFF_RS);

    const int tid  = threadIdx.x;
    const int row0 = blockIdx.x * ROWS;

    if (tid < 256) wls[tid] = wl[tid];
    if (tid < 128) rowsum[tid] = 0.f;

    // ---- stage A fragments: x fp32 -> fp16, mma a-fragment order ----
    for (int it = tid; it < 4096; it += 512) {
        int ln = it & 31;
        int kb = (it >> 5) & 15;
        int rg = it >> 9;
        int g = ln >> 2, tg = ln & 3;
        int r0 = rg * 16 + g, r1 = r0 + 8;
        int c0 = kb * 16 + tg * 2;
        int gr0 = row0 + r0, gr1 = row0 + r1;
        float2 z2 = make_float2(0.f, 0.f);
        float2 v00 = (gr0 < Bn) ? *reinterpret_cast<const float2*>(x + (size_t)gr0 * N_FEAT + c0)     : z2;
        float2 v01 = (gr0 < Bn) ? *reinterpret_cast<const float2*>(x + (size_t)gr0 * N_FEAT + c0 + 8) : z2;
        float2 v10 = (gr1 < Bn) ? *reinterpret_cast<const float2*>(x + (size_t)gr1 * N_FEAT + c0)     : z2;
        float2 v11 = (gr1 < Bn) ? *reinterpret_cast<const float2*>(x + (size_t)gr1 * N_FEAT + c0 + 8) : z2;
        __half2 h00 = __floats2half2_rn(v00.x, v00.y);
        __half2 h10 = __floats2half2_rn(v10.x, v10.y);
        __half2 h01 = __floats2half2_rn(v01.x, v01.y);
        __half2 h11 = __floats2half2_rn(v11.x, v11.y);
        uint4 o;
        o.x = *reinterpret_cast<uint32_t*>(&h00);
        o.y = *reinterpret_cast<uint32_t*>(&h10);
        o.z = *reinterpret_cast<uint32_t*>(&h01);
        o.w = *reinterpret_cast<uint32_t*>(&h11);
        afrag[(rg * 16 + kb) * 32 + ln] = o;
    }
    __syncthreads();

    const int wid = tid >> 5, lane = tid & 31;
    const int rg = wid >> 1, jhalf = wid & 1;
    const int g = lane >> 2, tg = lane & 3;

    float partial0 = 0.f, partial1 = 0.f;

    for (int jt = 0; jt < 4; ++jt) {            // runtime loop: small live set
        float acc[4][4];
#pragma unroll
        for (int s = 0; s < 4; ++s)
#pragma unroll
            for (int q = 0; q < 4; ++q) acc[s][q] = 0.f;

        const uint4* ap = &afrag[(rg * 16 + 4 * jt) * 32 + lane];
        const uint4* bp = &g_Bf[(((jt * 16 + 4 * jt) * 2 + jhalf) * 2) * 32 + lane];
        const int nuni = 12 - 4 * jt;           // uniform k-blocks after the diagonal 4

        // ---- diagonal 4 k-blocks, peeled, loads issued ahead of consuming mmas ----
        uint4 a0 = ap[0];
        uint4 p00 = bp[0];
        uint4 a1 = ap[32], p01 = bp[128];
        mma_f16(acc[0], a0, p00.x, p00.y);

        uint4 a2 = ap[64], p02 = bp[256], p12 = bp[256 + 32];
        mma_f16(acc[0], a1, p01.x, p01.y);
        mma_f16(acc[1], a1, p01.z, p01.w);

        uint4 a3 = ap[96], p03 = bp[384], p13 = bp[384 + 32];
        mma_f16(acc[0], a2, p02.x, p02.y);
        mma_f16(acc[1], a2, p02.z, p02.w);
        mma_f16(acc[2], a2, p12.x, p12.y);

        uint4 a_cur, p0_cur, p1_cur;
        if (nuni > 0) { a_cur = ap[128]; p0_cur = bp[512]; p1_cur = bp[512 + 32]; }
        mma_f16(acc[0], a3, p03.x, p03.y);
        mma_f16(acc[1], a3, p03.z, p03.w);
        mma_f16(acc[2], a3, p13.x, p13.y);
        mma_f16(acc[3], a3, p13.z, p13.w);

        ap += 128; bp += 512;

        // ---- uniform region with 1-deep prefetch ----
        for (int u = 0; u < nuni; ++u) {
            uint4 a_nxt, p0_nxt, p1_nxt;
            if (u + 1 < nuni) { a_nxt = ap[32]; p0_nxt = bp[128]; p1_nxt = bp[128 + 32]; }
            mma_f16(acc[0], a_cur, p0_cur.x, p0_cur.y);
            mma_f16(acc[1], a_cur, p0_cur.z, p0_cur.w);
            mma_f16(acc[2], a_cur, p1_cur.x, p1_cur.y);
            mma_f16(acc[3], a_cur, p1_cur.z, p1_cur.w);
            a_cur = a_nxt; p0_cur = p0_nxt; p1_cur = p1_nxt;
            ap += 32; bp += 128;
        }

        // ---- fused epilogue: partial += (Z + w) .* x over this warp's 32 cols ----
        // acc[s] <-> sub = jhalf + 2s; x from afrag kb' = 4jt+s, jhalf picks half.
#pragma unroll
        for (int s = 0; s < 4; ++s) {
            uint4 av = afrag[(rg * 16 + 4 * jt + s) * 32 + lane];
            uint32_t wlo = jhalf ? av.z : av.x;   // row g
            uint32_t whi = jhalf ? av.w : av.y;   // row g+8
            int sub = jhalf + 2 * s;
            int jb = jt * 64 + sub * 8 + tg * 2;
            float w0 = wls[jb], w1 = wls[jb + 1];
            float2 x0 = __half22float2(*reinterpret_cast<__half2*>(&wlo));
            float2 x1 = __half22float2(*reinterpret_cast<__half2*>(&whi));
            partial0 += (acc[s][0] + w0) * x0.x + (acc[s][1] + w1) * x0.y;
            partial1 += (acc[s][2] + w0) * x1.x + (acc[s][3] + w1) * x1.y;
        }
    }

    // reduce over the 4 lanes (tg) sharing each row
    partial0 += __shfl_xor_sync(0xffffffffu, partial0, 1);
    partial0 += __shfl_xor_sync(0xffffffffu, partial0, 2);
    partial1 += __shfl_xor_sync(0xffffffffu, partial1, 1);
    partial1 += __shfl_xor_sync(0xffffffffu, partial1, 2);

    if (tg == 0) {
        atomicAdd(&rowsum[rg * 16 + g],     partial0);
        atomicAdd(&rowsum[rg * 16 + g + 8], partial1);
    }
    __syncthreads();

    if (tid < 128) {
        int gr = row0 + tid;
        if (gr < Bn) out[gr] = rowsum[tid] + bl[0];
    }
}

// ---------------------------------------------------------------------------
extern "C" void kernel_launch(void* const* d_in, const int* in_sizes, int n_in,
                              void* d_out, int out_size) {
    const float* x    = (const float*)d_in[0];
    const float* wlin = (const float*)d_in[1];
    const float* blin = (const float*)d_in[2];
    const float* v    = (const float*)d_in[3];
    const int*   fidx = (const int*)d_in[4];
    float* out = (float*)d_out;

    int Bn = in_sizes[0] / N_FEAT;

    ffm_prep<<<32, 512>>>(v, fidx);

    cudaFuncSetAttribute(ffm_main, cudaFuncAttributeMaxDynamicSharedMemorySize, SMEM_TOTAL);
    int grid = (Bn + ROWS - 1) / ROWS;
    ffm_main<<<grid, 512, SMEM_TOTAL>>>(x, wlin, blin, out, Bn);
}